// round 1
// baseline (speedup 1.0000x reference)
#include <cuda_runtime.h>

#define N_NODES 100000
#define N_EDGES 1600000
#define C 128

// ---------------- static scratch (no allocations allowed) ----------------
__device__ float g_ni[(size_t)N_NODES * C];
__device__ float g_h [(size_t)N_NODES * C];
__device__ float g_hs[(size_t)N_NODES * C];
__device__ float g_g [(size_t)N_NODES * C];
__device__ float g_h2[(size_t)N_NODES * C];
__device__ float g_dis[N_NODES];
__device__ int   g_deg[N_NODES];
__device__ int   g_rowptr[N_NODES];
__device__ int   g_cursor[N_NODES];
__device__ int   g_csrsrc[N_EDGES];
__device__ int   g_bsum[128];

#define SCAN_BLK 1024
#define SCAN_NB  ((N_NODES + SCAN_BLK - 1) / SCAN_BLK)   // 98

// ---------------- CSR build ----------------
__global__ void k_zero_nodes() {
    int i = blockIdx.x * blockDim.x + threadIdx.x;
    if (i < N_NODES) { g_deg[i] = 0; g_cursor[i] = 0; }
}

__global__ void k_hist(const int* __restrict__ dst) {
    int e = blockIdx.x * blockDim.x + threadIdx.x;
    if (e < N_EDGES) atomicAdd(&g_deg[dst[e]], 1);
}

__global__ void k_dis() {
    int i = blockIdx.x * blockDim.x + threadIdx.x;
    if (i < N_NODES) g_dis[i] = rsqrtf((float)g_deg[i] + 1.0f);
}

__global__ void __launch_bounds__(SCAN_BLK) k_scan_a() {
    __shared__ int s[SCAN_BLK];
    int tid = threadIdx.x;
    int i = blockIdx.x * SCAN_BLK + tid;
    int v = (i < N_NODES) ? g_deg[i] : 0;
    s[tid] = v;
    __syncthreads();
    #pragma unroll
    for (int off = 1; off < SCAN_BLK; off <<= 1) {
        int t = (tid >= off) ? s[tid - off] : 0;
        __syncthreads();
        s[tid] += t;
        __syncthreads();
    }
    int incl = s[tid];
    if (i < N_NODES) g_rowptr[i] = incl - v;          // exclusive scan (per-block)
    if (tid == SCAN_BLK - 1) g_bsum[blockIdx.x] = incl;
}

__global__ void k_scan_b() {
    if (threadIdx.x == 0 && blockIdx.x == 0) {
        int run = 0;
        for (int b = 0; b < SCAN_NB; b++) { int t = g_bsum[b]; g_bsum[b] = run; run += t; }
    }
}

__global__ void __launch_bounds__(SCAN_BLK) k_scan_c() {
    int i = blockIdx.x * SCAN_BLK + threadIdx.x;
    if (i < N_NODES) g_rowptr[i] += g_bsum[blockIdx.x];
}

__global__ void k_fill(const int* __restrict__ src, const int* __restrict__ dst) {
    int e = blockIdx.x * blockDim.x + threadIdx.x;
    if (e < N_EDGES) {
        int d = dst[e];
        int pos = atomicAdd(&g_cursor[d], 1);
        g_csrsrc[g_rowptr[d] + pos] = src[e];
    }
}

// ---------------- preproc: h0 = x@Wp+bp; ni = relu(h0@W1+b1); h = relu(h0@W2+b2) ----------------
__global__ void __launch_bounds__(128) k_pre(
    const float* __restrict__ x,
    const float* __restrict__ Wp, const float* __restrict__ bp,
    const float* __restrict__ W1, const float* __restrict__ b1,
    const float* __restrict__ W2, const float* __restrict__ b2)
{
    __shared__ float sWp[8 * 32];
    __shared__ float sW1[32 * 128];
    __shared__ float sW2[32 * 128];
    __shared__ float sbp[32], sb1[128], sb2[128];
    __shared__ float xs[32][8];
    __shared__ float h0s[32][33];

    int tid = threadIdx.x;
    for (int i = tid; i < 8 * 32; i += 128) sWp[i] = Wp[i];
    for (int i = tid; i < 32 * 128; i += 128) { sW1[i] = W1[i]; sW2[i] = W2[i]; }
    if (tid < 32) sbp[tid] = bp[tid];
    sb1[tid] = b1[tid];
    sb2[tid] = b2[tid];

    int n0 = blockIdx.x * 32;
    for (int i = tid; i < 32 * 8; i += 128) {
        int n = i >> 3, f = i & 7;
        xs[n][f] = x[(size_t)(n0 + n) * 8 + f];
    }
    __syncthreads();

    for (int i = tid; i < 32 * 32; i += 128) {
        int n = i >> 5, j = i & 31;
        float s = sbp[j];
        #pragma unroll
        for (int f = 0; f < 8; f++) s = fmaf(xs[n][f], sWp[f * 32 + j], s);
        h0s[n][j] = s;
    }
    __syncthreads();

    int c = tid;
    for (int n = 0; n < 32; n++) {
        int row = n0 + n;
        float s1 = sb1[c], s2 = sb2[c];
        #pragma unroll
        for (int k = 0; k < 32; k++) {
            float hv = h0s[n][k];
            s1 = fmaf(hv, sW1[k * 128 + c], s1);
            s2 = fmaf(hv, sW2[k * 128 + c], s2);
        }
        g_ni[(size_t)row * C + c] = fmaxf(s1, 0.f);
        g_h [(size_t)row * C + c] = fmaxf(s2, 0.f);
    }
}

// ---------------- SGEMM: out[M,128] = A[M,KTOT] @ W[KTOT,128] ----------------
// MODE 0: A = g_h (K=128); epilogue hs = acc * dis[row]            -> out = g_hs
// MODE 1: A = [A1 | A2]   (K=256); epilogue out = relu(acc + bias) -> out
template<int KTOT, int MODE>
__global__ void __launch_bounds__(256) k_gemm(
    const float* __restrict__ A1, const float* __restrict__ A2,
    const float* __restrict__ W, const float* __restrict__ bias,
    float* __restrict__ out)
{
    __shared__ float As[128][17];
    __shared__ float Bs[16][128];

    int m0 = blockIdx.x * 128;
    int tid = threadIdx.x;
    int tx = tid & 15, ty = tid >> 4;

    float acc[8][8];
    #pragma unroll
    for (int i = 0; i < 8; i++)
        #pragma unroll
        for (int j = 0; j < 8; j++) acc[i][j] = 0.f;

    for (int kt = 0; kt < KTOT; kt += 16) {
        const float* Asrc = A1;
        int koff = kt;
        if (KTOT == 256 && kt >= 128) { Asrc = A2; koff = kt - 128; }

        #pragma unroll
        for (int p = 0; p < 8; p++) {
            int idx = p * 256 + tid;
            int r = idx >> 4, k = idx & 15;
            int row = m0 + r;
            As[r][k] = (row < N_NODES) ? Asrc[(size_t)row * C + koff + k] : 0.f;
        }
        #pragma unroll
        for (int p = 0; p < 8; p++) {
            int idx = p * 256 + tid;
            int k = idx >> 7, cc = idx & 127;
            Bs[k][cc] = W[(size_t)(kt + k) * C + cc];
        }
        __syncthreads();

        #pragma unroll
        for (int k = 0; k < 16; k++) {
            float a[8], b[8];
            #pragma unroll
            for (int i = 0; i < 8; i++) a[i] = As[ty * 8 + i][k];
            float4 b0 = *(const float4*)&Bs[k][tx * 8];
            float4 b1 = *(const float4*)&Bs[k][tx * 8 + 4];
            b[0] = b0.x; b[1] = b0.y; b[2] = b0.z; b[3] = b0.w;
            b[4] = b1.x; b[5] = b1.y; b[6] = b1.z; b[7] = b1.w;
            #pragma unroll
            for (int i = 0; i < 8; i++)
                #pragma unroll
                for (int j = 0; j < 8; j++)
                    acc[i][j] = fmaf(a[i], b[j], acc[i][j]);
        }
        __syncthreads();
    }

    if (MODE == 0) {
        #pragma unroll
        for (int i = 0; i < 8; i++) {
            int row = m0 + ty * 8 + i;
            if (row >= N_NODES) continue;
            float d = g_dis[row];
            float4 v0 = make_float4(acc[i][0] * d, acc[i][1] * d, acc[i][2] * d, acc[i][3] * d);
            float4 v1 = make_float4(acc[i][4] * d, acc[i][5] * d, acc[i][6] * d, acc[i][7] * d);
            *(float4*)&out[(size_t)row * C + tx * 8]     = v0;
            *(float4*)&out[(size_t)row * C + tx * 8 + 4] = v1;
        }
    } else {
        float4 bb0 = *(const float4*)&bias[tx * 8];
        float4 bb1 = *(const float4*)&bias[tx * 8 + 4];
        #pragma unroll
        for (int i = 0; i < 8; i++) {
            int row = m0 + ty * 8 + i;
            if (row >= N_NODES) continue;
            float4 v0 = make_float4(fmaxf(acc[i][0] + bb0.x, 0.f), fmaxf(acc[i][1] + bb0.y, 0.f),
                                    fmaxf(acc[i][2] + bb0.z, 0.f), fmaxf(acc[i][3] + bb0.w, 0.f));
            float4 v1 = make_float4(fmaxf(acc[i][4] + bb1.x, 0.f), fmaxf(acc[i][5] + bb1.y, 0.f),
                                    fmaxf(acc[i][6] + bb1.z, 0.f), fmaxf(acc[i][7] + bb1.w, 0.f));
            *(float4*)&out[(size_t)row * C + tx * 8]     = v0;
            *(float4*)&out[(size_t)row * C + tx * 8 + 4] = v1;
        }
    }
}

// ---------------- aggregation: g = relu((hs[n] + sum_{j in N(n)} hs[j]) * dis[n] + bg) ----------------
__global__ void __launch_bounds__(256) k_agg(const float* __restrict__ bg) {
    int gt = blockIdx.x * blockDim.x + threadIdx.x;
    int w = gt >> 5;
    if (w >= N_NODES) return;
    int lane = threadIdx.x & 31;

    int base = g_rowptr[w];
    int deg  = g_deg[w];

    const float* hsrow = &g_hs[(size_t)w * C + lane * 4];
    float4 acc = *(const float4*)hsrow;   // self-loop term

    int j = 0;
    for (; j + 4 <= deg; j += 4) {
        int s0 = g_csrsrc[base + j];
        int s1 = g_csrsrc[base + j + 1];
        int s2 = g_csrsrc[base + j + 2];
        int s3 = g_csrsrc[base + j + 3];
        float4 v0 = *(const float4*)&g_hs[(size_t)s0 * C + lane * 4];
        float4 v1 = *(const float4*)&g_hs[(size_t)s1 * C + lane * 4];
        float4 v2 = *(const float4*)&g_hs[(size_t)s2 * C + lane * 4];
        float4 v3 = *(const float4*)&g_hs[(size_t)s3 * C + lane * 4];
        acc.x += v0.x + v1.x + v2.x + v3.x;
        acc.y += v0.y + v1.y + v2.y + v3.y;
        acc.z += v0.z + v1.z + v2.z + v3.z;
        acc.w += v0.w + v1.w + v2.w + v3.w;
    }
    for (; j < deg; j++) {
        int s = g_csrsrc[base + j];
        float4 v = *(const float4*)&g_hs[(size_t)s * C + lane * 4];
        acc.x += v.x; acc.y += v.y; acc.z += v.z; acc.w += v.w;
    }

    float d = g_dis[w];
    float4 bb = *(const float4*)&bg[lane * 4];
    float4 r;
    r.x = fmaxf(fmaf(acc.x, d, bb.x), 0.f);
    r.y = fmaxf(fmaf(acc.y, d, bb.y), 0.f);
    r.z = fmaxf(fmaf(acc.z, d, bb.z), 0.f);
    r.w = fmaxf(fmaf(acc.w, d, bb.w), 0.f);
    *(float4*)&g_g[(size_t)w * C + lane * 4] = r;
}

// ---------------- output: out[n,0:2] = h2[n,:] @ Wf2 + bf2 ----------------
__global__ void __launch_bounds__(256) k_out(
    const float* __restrict__ Wf2, const float* __restrict__ bf2, float* __restrict__ out)
{
    int gt = blockIdx.x * blockDim.x + threadIdx.x;
    int w = gt >> 5;
    if (w >= N_NODES) return;
    int lane = threadIdx.x & 31;

    float4 h = *(const float4*)&g_h2[(size_t)w * C + lane * 4];
    // Wf2 is [128,2] row-major: row k at Wf2[2k], Wf2[2k+1]
    float4 w01 = *(const float4*)&Wf2[lane * 8];       // rows lane*4, lane*4+1
    float4 w23 = *(const float4*)&Wf2[lane * 8 + 4];   // rows lane*4+2, lane*4+3

    float s0 = h.x * w01.x + h.y * w01.z + h.z * w23.x + h.w * w23.z;
    float s1 = h.x * w01.y + h.y * w01.w + h.z * w23.y + h.w * w23.w;

    #pragma unroll
    for (int off = 16; off > 0; off >>= 1) {
        s0 += __shfl_xor_sync(0xFFFFFFFF, s0, off);
        s1 += __shfl_xor_sync(0xFFFFFFFF, s1, off);
    }
    if (lane == 0) {
        out[(size_t)w * 2 + 0] = s0 + bf2[0];
        out[(size_t)w * 2 + 1] = s1 + bf2[1];
    }
}

// ---------------- host launcher ----------------
extern "C" void kernel_launch(void* const* d_in, const int* in_sizes, int n_in,
                              void* d_out, int out_size)
{
    const float* x   = (const float*)d_in[0];
    const int* ei    = (const int*)d_in[1];
    const float* Wp  = (const float*)d_in[2];
    const float* bp  = (const float*)d_in[3];
    const float* W1  = (const float*)d_in[4];
    const float* b1  = (const float*)d_in[5];
    const float* W2  = (const float*)d_in[6];
    const float* b2  = (const float*)d_in[7];
    const float* Wg  = (const float*)d_in[8];
    const float* bg  = (const float*)d_in[9];
    const float* Wd  = (const float*)d_in[10];
    const float* bd  = (const float*)d_in[11];
    const float* Wf1 = (const float*)d_in[12];
    const float* bf1 = (const float*)d_in[13];
    const float* Wf2 = (const float*)d_in[14];
    const float* bf2 = (const float*)d_in[15];
    float* out = (float*)d_out;

    const int* src = ei;
    const int* dst = ei + N_EDGES;

    float* d_ni = nullptr;  cudaGetSymbolAddress((void**)&d_ni, g_ni);
    float* d_h  = nullptr;  cudaGetSymbolAddress((void**)&d_h,  g_h);
    float* d_hs = nullptr;  cudaGetSymbolAddress((void**)&d_hs, g_hs);
    float* d_g  = nullptr;  cudaGetSymbolAddress((void**)&d_g,  g_g);
    float* d_h2 = nullptr;  cudaGetSymbolAddress((void**)&d_h2, g_h2);

    // CSR build (once per launch)
    k_zero_nodes<<<(N_NODES + 255) / 256, 256>>>();
    k_hist<<<(N_EDGES + 255) / 256, 256>>>(dst);
    k_dis<<<(N_NODES + 255) / 256, 256>>>();
    k_scan_a<<<SCAN_NB, SCAN_BLK>>>();
    k_scan_b<<<1, 32>>>();
    k_scan_c<<<SCAN_NB, SCAN_BLK>>>();
    k_fill<<<(N_EDGES + 255) / 256, 256>>>(src, dst);

    // preprocessing
    k_pre<<<N_NODES / 32, 128>>>(x, Wp, bp, W1, b1, W2, b2);

    const int MB = (N_NODES + 127) / 128;          // 782
    const int WPB = (N_NODES * 32 + 255) / 256;    // warp-per-node grids

    for (int l = 0; l < 8; l++) {
        k_gemm<128, 0><<<MB, 256>>>(d_h, nullptr, Wg, nullptr, d_hs);
        k_agg<<<WPB, 256>>>(bg);
        k_gemm<256, 1><<<MB, 256>>>(d_ni, d_g, Wd, bd, d_h);
    }

    k_gemm<256, 1><<<MB, 256>>>(d_ni, d_h, Wf1, bf1, d_h2);
    k_out<<<WPB, 256>>>(Wf2, bf2, out);
}

// round 2
// speedup vs baseline: 1.1085x; 1.1085x over previous
#include <cuda_runtime.h>

#define N_NODES 100000
#define N_EDGES 1600000
#define C 128

// ---------------- static scratch (no allocations allowed) ----------------
__device__ float g_ni  [(size_t)N_NODES * C];
__device__ float g_h   [(size_t)N_NODES * C];
__device__ float g_hs  [(size_t)N_NODES * C];
__device__ float g_g   [(size_t)N_NODES * C];
__device__ float g_h2  [(size_t)N_NODES * C];
__device__ float g_pre [(size_t)N_NODES * C];   // ni @ Wd[:128] + bd
__device__ float g_pref[(size_t)N_NODES * C];   // ni @ Wf1[:128] + bf1
__device__ float g_dis[N_NODES];
__device__ int   g_deg[N_NODES];
__device__ int   g_rowptr[N_NODES];
__device__ int   g_cursor[N_NODES];
__device__ int   g_csrsrc[N_EDGES];
__device__ int   g_bsum[128];

#define SCAN_BLK 1024
#define SCAN_NB  ((N_NODES + SCAN_BLK - 1) / SCAN_BLK)   // 98

// ---------------- CSR build ----------------
__global__ void k_zero_nodes() {
    int i = blockIdx.x * blockDim.x + threadIdx.x;
    if (i < N_NODES) { g_deg[i] = 0; g_cursor[i] = 0; }
}

__global__ void k_hist(const int* __restrict__ dst) {
    int e = blockIdx.x * blockDim.x + threadIdx.x;
    if (e < N_EDGES) atomicAdd(&g_deg[dst[e]], 1);
}

__global__ void k_dis() {
    int i = blockIdx.x * blockDim.x + threadIdx.x;
    if (i < N_NODES) g_dis[i] = rsqrtf((float)g_deg[i] + 1.0f);
}

__global__ void __launch_bounds__(SCAN_BLK) k_scan_a() {
    __shared__ int s[SCAN_BLK];
    int tid = threadIdx.x;
    int i = blockIdx.x * SCAN_BLK + tid;
    int v = (i < N_NODES) ? g_deg[i] : 0;
    s[tid] = v;
    __syncthreads();
    #pragma unroll
    for (int off = 1; off < SCAN_BLK; off <<= 1) {
        int t = (tid >= off) ? s[tid - off] : 0;
        __syncthreads();
        s[tid] += t;
        __syncthreads();
    }
    int incl = s[tid];
    if (i < N_NODES) g_rowptr[i] = incl - v;
    if (tid == SCAN_BLK - 1) g_bsum[blockIdx.x] = incl;
}

__global__ void k_scan_b() {
    if (threadIdx.x == 0 && blockIdx.x == 0) {
        int run = 0;
        for (int b = 0; b < SCAN_NB; b++) { int t = g_bsum[b]; g_bsum[b] = run; run += t; }
    }
}

__global__ void __launch_bounds__(SCAN_BLK) k_scan_c() {
    int i = blockIdx.x * SCAN_BLK + threadIdx.x;
    if (i < N_NODES) g_rowptr[i] += g_bsum[blockIdx.x];
}

__global__ void k_fill(const int* __restrict__ src, const int* __restrict__ dst) {
    int e = blockIdx.x * blockDim.x + threadIdx.x;
    if (e < N_EDGES) {
        int d = dst[e];
        int pos = atomicAdd(&g_cursor[d], 1);
        g_csrsrc[g_rowptr[d] + pos] = src[e];
    }
}

// ---------------- preproc: h0 = x@Wp+bp; ni = relu(h0@W1+b1); h = relu(h0@W2+b2) ----------------
__global__ void __launch_bounds__(128) k_pre(
    const float* __restrict__ x,
    const float* __restrict__ Wp, const float* __restrict__ bp,
    const float* __restrict__ W1, const float* __restrict__ b1,
    const float* __restrict__ W2, const float* __restrict__ b2)
{
    __shared__ float sWp[8 * 32];
    __shared__ float sW1[32 * 128];
    __shared__ float sW2[32 * 128];
    __shared__ float sbp[32], sb1[128], sb2[128];
    __shared__ float xs[32][8];
    __shared__ float h0s[32][33];

    int tid = threadIdx.x;
    for (int i = tid; i < 8 * 32; i += 128) sWp[i] = Wp[i];
    for (int i = tid; i < 32 * 128; i += 128) { sW1[i] = W1[i]; sW2[i] = W2[i]; }
    if (tid < 32) sbp[tid] = bp[tid];
    sb1[tid] = b1[tid];
    sb2[tid] = b2[tid];

    int n0 = blockIdx.x * 32;
    for (int i = tid; i < 32 * 8; i += 128) {
        int n = i >> 3, f = i & 7;
        xs[n][f] = x[(size_t)(n0 + n) * 8 + f];
    }
    __syncthreads();

    for (int i = tid; i < 32 * 32; i += 128) {
        int n = i >> 5, j = i & 31;
        float s = sbp[j];
        #pragma unroll
        for (int f = 0; f < 8; f++) s = fmaf(xs[n][f], sWp[f * 32 + j], s);
        h0s[n][j] = s;
    }
    __syncthreads();

    int c = tid;
    for (int n = 0; n < 32; n++) {
        int row = n0 + n;
        float s1 = sb1[c], s2 = sb2[c];
        #pragma unroll
        for (int k = 0; k < 32; k++) {
            float hv = h0s[n][k];
            s1 = fmaf(hv, sW1[k * 128 + c], s1);
            s2 = fmaf(hv, sW2[k * 128 + c], s2);
        }
        g_ni[(size_t)row * C + c] = fmaxf(s1, 0.f);
        g_h [(size_t)row * C + c] = fmaxf(s2, 0.f);
    }
}

// ---------------- packed-f32x2 SGEMM: out[M,128] = A[M,128] @ W[128,128] + epilogue ----------------
// MODE 0: out = acc * dis[row]                 (GCN pre-scale)
// MODE 1: out = relu(acc + P[row, :])          (layer fusion; P = precomputed ni-part)
// MODE 2: out = acc + bias[:]                  (precompute ni@Wd_top + bd)
#define FMA2(d, a, b) asm volatile("fma.rn.f32x2 %0, %1, %2, %0;" : "+l"(d) : "l"(a), "l"(b))

__device__ __forceinline__ float lo32(unsigned long long v) { return __uint_as_float((unsigned)v); }
__device__ __forceinline__ float hi32(unsigned long long v) { return __uint_as_float((unsigned)(v >> 32)); }

template<int MODE>
__global__ void __launch_bounds__(256) k_gemm2(
    const float* __restrict__ A, const float* __restrict__ W,
    const float* __restrict__ BP, float* __restrict__ out)
{
    __shared__ float As2[32][256];   // k-major, values duplicated: As2[k][2m]=As2[k][2m+1]=A[m][k]
    __shared__ float Bs [32][128];   // k-major

    int t = threadIdx.x;
    int m0 = blockIdx.x * 128;
    int tx = t & 15, ty = t >> 4;

    unsigned long long acc[8][4];
    #pragma unroll
    for (int i = 0; i < 8; i++)
        #pragma unroll
        for (int j = 0; j < 4; j++) acc[i][j] = 0ull;

    int lm = t & 127;
    int kq = (t >> 7) * 16;
    int lrow = m0 + lm;
    bool lvalid = lrow < N_NODES;

    for (int kt = 0; kt < 128; kt += 32) {
        // A tile -> duplicated k-major smem
        const float* ap = A + (size_t)lrow * C + kt + kq;
        #pragma unroll
        for (int j = 0; j < 4; j++) {
            float4 v = lvalid ? *(const float4*)(ap + 4 * j) : make_float4(0.f, 0.f, 0.f, 0.f);
            int k = kq + 4 * j;
            *(float2*)&As2[k + 0][2 * lm] = make_float2(v.x, v.x);
            *(float2*)&As2[k + 1][2 * lm] = make_float2(v.y, v.y);
            *(float2*)&As2[k + 2][2 * lm] = make_float2(v.z, v.z);
            *(float2*)&As2[k + 3][2 * lm] = make_float2(v.w, v.w);
        }
        // B tile (weights are row-major [k][c] already)
        #pragma unroll
        for (int p = 0; p < 4; p++) {
            int idx = (p * 256 + t) * 4;
            int k = idx >> 7, cc = idx & 127;
            *(float4*)&Bs[k][cc] = *(const float4*)&W[(size_t)(kt + k) * C + cc];
        }
        __syncthreads();

        #pragma unroll
        for (int k = 0; k < 32; k++) {
            ulonglong2 aA = *(const ulonglong2*)&As2[k][ty * 16];
            ulonglong2 aB = *(const ulonglong2*)&As2[k][ty * 16 + 4];
            ulonglong2 aC = *(const ulonglong2*)&As2[k][ty * 16 + 8];
            ulonglong2 aD = *(const ulonglong2*)&As2[k][ty * 16 + 12];
            ulonglong2 b0 = *(const ulonglong2*)&Bs[k][tx * 8];
            ulonglong2 b1 = *(const ulonglong2*)&Bs[k][tx * 8 + 4];
            unsigned long long apk[8] = {aA.x, aA.y, aB.x, aB.y, aC.x, aC.y, aD.x, aD.y};
            unsigned long long bpk[4] = {b0.x, b0.y, b1.x, b1.y};
            #pragma unroll
            for (int i = 0; i < 8; i++)
                #pragma unroll
                for (int j = 0; j < 4; j++)
                    FMA2(acc[i][j], apk[i], bpk[j]);
        }
        __syncthreads();
    }

    // epilogue
    #pragma unroll
    for (int i = 0; i < 8; i++) {
        int row = m0 + ty * 8 + i;
        if (row >= N_NODES) continue;
        float c0 = lo32(acc[i][0]), c1 = hi32(acc[i][0]);
        float c2 = lo32(acc[i][1]), c3 = hi32(acc[i][1]);
        float c4 = lo32(acc[i][2]), c5 = hi32(acc[i][2]);
        float c6 = lo32(acc[i][3]), c7 = hi32(acc[i][3]);
        float4 v0, v1;
        if (MODE == 0) {
            float d = g_dis[row];
            v0 = make_float4(c0 * d, c1 * d, c2 * d, c3 * d);
            v1 = make_float4(c4 * d, c5 * d, c6 * d, c7 * d);
        } else if (MODE == 1) {
            const float* p = BP + (size_t)row * C + tx * 8;
            float4 p0 = *(const float4*)p;
            float4 p1 = *(const float4*)(p + 4);
            v0 = make_float4(fmaxf(c0 + p0.x, 0.f), fmaxf(c1 + p0.y, 0.f),
                             fmaxf(c2 + p0.z, 0.f), fmaxf(c3 + p0.w, 0.f));
            v1 = make_float4(fmaxf(c4 + p1.x, 0.f), fmaxf(c5 + p1.y, 0.f),
                             fmaxf(c6 + p1.z, 0.f), fmaxf(c7 + p1.w, 0.f));
        } else {
            float4 b0 = *(const float4*)&BP[tx * 8];
            float4 b1 = *(const float4*)&BP[tx * 8 + 4];
            v0 = make_float4(c0 + b0.x, c1 + b0.y, c2 + b0.z, c3 + b0.w);
            v1 = make_float4(c4 + b1.x, c5 + b1.y, c6 + b1.z, c7 + b1.w);
        }
        *(float4*)&out[(size_t)row * C + tx * 8]     = v0;
        *(float4*)&out[(size_t)row * C + tx * 8 + 4] = v1;
    }
}

// ---------------- aggregation: g = relu((hs[n] + sum_{j in N(n)} hs[j]) * dis[n] + bg) ----------------
__global__ void __launch_bounds__(256) k_agg(const float* __restrict__ bg) {
    int gt = blockIdx.x * blockDim.x + threadIdx.x;
    int w = gt >> 5;
    if (w >= N_NODES) return;
    int lane = threadIdx.x & 31;

    int base = g_rowptr[w];
    int deg  = g_deg[w];

    float4 acc = *(const float4*)&g_hs[(size_t)w * C + lane * 4];   // self-loop term

    int j = 0;
    for (; j + 4 <= deg; j += 4) {
        int s0 = g_csrsrc[base + j];
        int s1 = g_csrsrc[base + j + 1];
        int s2 = g_csrsrc[base + j + 2];
        int s3 = g_csrsrc[base + j + 3];
        float4 v0 = *(const float4*)&g_hs[(size_t)s0 * C + lane * 4];
        float4 v1 = *(const float4*)&g_hs[(size_t)s1 * C + lane * 4];
        float4 v2 = *(const float4*)&g_hs[(size_t)s2 * C + lane * 4];
        float4 v3 = *(const float4*)&g_hs[(size_t)s3 * C + lane * 4];
        acc.x += v0.x + v1.x + v2.x + v3.x;
        acc.y += v0.y + v1.y + v2.y + v3.y;
        acc.z += v0.z + v1.z + v2.z + v3.z;
        acc.w += v0.w + v1.w + v2.w + v3.w;
    }
    for (; j < deg; j++) {
        int s = g_csrsrc[base + j];
        float4 v = *(const float4*)&g_hs[(size_t)s * C + lane * 4];
        acc.x += v.x; acc.y += v.y; acc.z += v.z; acc.w += v.w;
    }

    float d = g_dis[w];
    float4 bb = *(const float4*)&bg[lane * 4];
    float4 r;
    r.x = fmaxf(fmaf(acc.x, d, bb.x), 0.f);
    r.y = fmaxf(fmaf(acc.y, d, bb.y), 0.f);
    r.z = fmaxf(fmaf(acc.z, d, bb.z), 0.f);
    r.w = fmaxf(fmaf(acc.w, d, bb.w), 0.f);
    *(float4*)&g_g[(size_t)w * C + lane * 4] = r;
}

// ---------------- output: out[n,0:2] = h2[n,:] @ Wf2 + bf2 ----------------
__global__ void __launch_bounds__(256) k_out(
    const float* __restrict__ Wf2, const float* __restrict__ bf2, float* __restrict__ out)
{
    int gt = blockIdx.x * blockDim.x + threadIdx.x;
    int w = gt >> 5;
    if (w >= N_NODES) return;
    int lane = threadIdx.x & 31;

    float4 h = *(const float4*)&g_h2[(size_t)w * C + lane * 4];
    float4 w01 = *(const float4*)&Wf2[lane * 8];
    float4 w23 = *(const float4*)&Wf2[lane * 8 + 4];

    float s0 = h.x * w01.x + h.y * w01.z + h.z * w23.x + h.w * w23.z;
    float s1 = h.x * w01.y + h.y * w01.w + h.z * w23.y + h.w * w23.w;

    #pragma unroll
    for (int off = 16; off > 0; off >>= 1) {
        s0 += __shfl_xor_sync(0xFFFFFFFF, s0, off);
        s1 += __shfl_xor_sync(0xFFFFFFFF, s1, off);
    }
    if (lane == 0) {
        out[(size_t)w * 2 + 0] = s0 + bf2[0];
        out[(size_t)w * 2 + 1] = s1 + bf2[1];
    }
}

// ---------------- host launcher ----------------
extern "C" void kernel_launch(void* const* d_in, const int* in_sizes, int n_in,
                              void* d_out, int out_size)
{
    const float* x   = (const float*)d_in[0];
    const int* ei    = (const int*)d_in[1];
    const float* Wp  = (const float*)d_in[2];
    const float* bp  = (const float*)d_in[3];
    const float* W1  = (const float*)d_in[4];
    const float* b1  = (const float*)d_in[5];
    const float* W2  = (const float*)d_in[6];
    const float* b2  = (const float*)d_in[7];
    const float* Wg  = (const float*)d_in[8];
    const float* bg  = (const float*)d_in[9];
    const float* Wd  = (const float*)d_in[10];
    const float* bd  = (const float*)d_in[11];
    const float* Wf1 = (const float*)d_in[12];
    const float* bf1 = (const float*)d_in[13];
    const float* Wf2 = (const float*)d_in[14];
    const float* bf2 = (const float*)d_in[15];
    float* out = (float*)d_out;

    const int* src = ei;
    const int* dst = ei + N_EDGES;

    float* d_ni = nullptr;   cudaGetSymbolAddress((void**)&d_ni,   g_ni);
    float* d_h  = nullptr;   cudaGetSymbolAddress((void**)&d_h,    g_h);
    float* d_hs = nullptr;   cudaGetSymbolAddress((void**)&d_hs,   g_hs);
    float* d_g  = nullptr;   cudaGetSymbolAddress((void**)&d_g,    g_g);
    float* d_h2 = nullptr;   cudaGetSymbolAddress((void**)&d_h2,   g_h2);
    float* d_pre = nullptr;  cudaGetSymbolAddress((void**)&d_pre,  g_pre);
    float* d_pref = nullptr; cudaGetSymbolAddress((void**)&d_pref, g_pref);

    const float* WdA  = Wd;            // rows 0..127  (ni part)
    const float* WdB  = Wd + 128 * C;  // rows 128..255 (g part)
    const float* Wf1A = Wf1;
    const float* Wf1B = Wf1 + 128 * C;

    const int MB  = (N_NODES + 127) / 128;        // 782
    const int WPB = (N_NODES * 32 + 255) / 256;

    // ordering chosen so the ncu capture window lands on a GEMM
    k_zero_nodes<<<(N_NODES + 255) / 256, 256>>>();
    k_pre<<<N_NODES / 32, 128>>>(x, Wp, bp, W1, b1, W2, b2);
    k_hist<<<(N_EDGES + 255) / 256, 256>>>(dst);
    k_dis<<<(N_NODES + 255) / 256, 256>>>();
    k_gemm2<2><<<MB, 256>>>(d_ni, WdA,  bd,  d_pre);   // pre  = ni@WdA  + bd
    k_gemm2<2><<<MB, 256>>>(d_ni, Wf1A, bf1, d_pref);  // pref = ni@Wf1A + bf1
    k_gemm2<0><<<MB, 256>>>(d_h, Wg, nullptr, d_hs);   // layer 1 GCN GEMM
    k_scan_a<<<SCAN_NB, SCAN_BLK>>>();
    k_scan_b<<<1, 32>>>();
    k_scan_c<<<SCAN_NB, SCAN_BLK>>>();
    k_fill<<<(N_EDGES + 255) / 256, 256>>>(src, dst);

    for (int l = 0; l < 8; l++) {
        if (l > 0) k_gemm2<0><<<MB, 256>>>(d_h, Wg, nullptr, d_hs);
        k_agg<<<WPB, 256>>>(bg);
        k_gemm2<1><<<MB, 256>>>(d_g, WdB, d_pre, d_h);  // h = relu(g@WdB + pre)
    }

    k_gemm2<1><<<MB, 256>>>(d_h, Wf1B, d_pref, d_h2);   // h2 = relu(h@Wf1B + pref)
    k_out<<<WPB, 256>>>(Wf2, bf2, out);
}

// round 4
// speedup vs baseline: 1.8206x; 1.6425x over previous
#include <cuda_runtime.h>
#include <cuda_bf16.h>
#include <cstdint>

#define N_NODES 100000
#define N_EDGES 1600000
#define C 128

// ---------------- static scratch (no allocations allowed) ----------------
__device__ float g_ni  [(size_t)N_NODES * C];
__device__ float g_h   [(size_t)N_NODES * C];
__device__ float g_hs  [(size_t)N_NODES * C];
__device__ float g_g   [(size_t)N_NODES * C];
__device__ float g_h2  [(size_t)N_NODES * C];
__device__ float g_pre [(size_t)N_NODES * C];   // ni @ Wd[:128] + bd
__device__ float g_pref[(size_t)N_NODES * C];   // ni @ Wf1[:128] + bf1
__device__ float g_dis[N_NODES];
__device__ int   g_deg[N_NODES];
__device__ int   g_rowptr[N_NODES];
__device__ int   g_cursor[N_NODES];
__device__ int   g_csrsrc[N_EDGES];
__device__ int   g_bsum[128];

// bf16 hi/lo weights (original [k][n] layout): slots {0:Wg, 1:WdA, 2:WdB, 3:Wf1A, 4:Wf1B}
__device__ __nv_bfloat16 g_whi[5 * 128 * 128];
__device__ __nv_bfloat16 g_wlo[5 * 128 * 128];

#define SCAN_BLK 1024
#define SCAN_NB  ((N_NODES + SCAN_BLK - 1) / SCAN_BLK)   // 98

// ---------------- PTX helpers (sm_80-era only: ldmatrix + mma.sync) ----------------
__device__ __forceinline__ uint32_t smem_u32(const void* p) {
    uint32_t a;
    asm("{ .reg .u64 t; cvta.to.shared.u64 t, %1; cvt.u32.u64 %0, t; }" : "=r"(a) : "l"(p));
    return a;
}

#define LDSM_X4(r, addr) \
    asm volatile("ldmatrix.sync.aligned.m8n8.x4.shared.b16 {%0,%1,%2,%3}, [%4];" \
        : "=r"((r)[0]), "=r"((r)[1]), "=r"((r)[2]), "=r"((r)[3]) : "r"(addr))

#define LDSM_X4T(r, addr) \
    asm volatile("ldmatrix.sync.aligned.m8n8.x4.trans.shared.b16 {%0,%1,%2,%3}, [%4];" \
        : "=r"((r)[0]), "=r"((r)[1]), "=r"((r)[2]), "=r"((r)[3]) : "r"(addr))

__device__ __forceinline__ void mma_bf16(float* c, const uint32_t* a, const uint32_t* b) {
    asm volatile("mma.sync.aligned.m16n8k16.row.col.f32.bf16.bf16.f32 "
        "{%0,%1,%2,%3}, {%4,%5,%6,%7}, {%8,%9}, {%0,%1,%2,%3};"
        : "+f"(c[0]), "+f"(c[1]), "+f"(c[2]), "+f"(c[3])
        : "r"(a[0]), "r"(a[1]), "r"(a[2]), "r"(a[3]), "r"(b[0]), "r"(b[1]));
}

// ---------------- CSR build ----------------
__global__ void k_zero_nodes() {
    int i = blockIdx.x * blockDim.x + threadIdx.x;
    if (i < N_NODES) { g_deg[i] = 0; g_cursor[i] = 0; }
}
__global__ void k_hist(const int* __restrict__ dst) {
    int e = blockIdx.x * blockDim.x + threadIdx.x;
    if (e < N_EDGES) atomicAdd(&g_deg[dst[e]], 1);
}
__global__ void k_dis() {
    int i = blockIdx.x * blockDim.x + threadIdx.x;
    if (i < N_NODES) g_dis[i] = rsqrtf((float)g_deg[i] + 1.0f);
}
__global__ void __launch_bounds__(SCAN_BLK) k_scan_a() {
    __shared__ int s[SCAN_BLK];
    int tid = threadIdx.x;
    int i = blockIdx.x * SCAN_BLK + tid;
    int v = (i < N_NODES) ? g_deg[i] : 0;
    s[tid] = v;
    __syncthreads();
    #pragma unroll
    for (int off = 1; off < SCAN_BLK; off <<= 1) {
        int t = (tid >= off) ? s[tid - off] : 0;
        __syncthreads();
        s[tid] += t;
        __syncthreads();
    }
    int incl = s[tid];
    if (i < N_NODES) g_rowptr[i] = incl - v;
    if (tid == SCAN_BLK - 1) g_bsum[blockIdx.x] = incl;
}
__global__ void k_scan_b() {
    if (threadIdx.x == 0 && blockIdx.x == 0) {
        int run = 0;
        for (int b = 0; b < SCAN_NB; b++) { int t = g_bsum[b]; g_bsum[b] = run; run += t; }
    }
}
__global__ void __launch_bounds__(SCAN_BLK) k_scan_c() {
    int i = blockIdx.x * SCAN_BLK + threadIdx.x;
    if (i < N_NODES) g_rowptr[i] += g_bsum[blockIdx.x];
}
__global__ void k_fill(const int* __restrict__ src, const int* __restrict__ dst) {
    int e = blockIdx.x * blockDim.x + threadIdx.x;
    if (e < N_EDGES) {
        int d = dst[e];
        int pos = atomicAdd(&g_cursor[d], 1);
        g_csrsrc[g_rowptr[d] + pos] = src[e];
    }
}

// ---------------- weight prep: split W[k][n] fp32 -> bf16 hi/lo (same layout) ----------------
__global__ void k_wprep(const float* __restrict__ W, __nv_bfloat16* __restrict__ hi,
                        __nv_bfloat16* __restrict__ lo) {
    int idx = blockIdx.x * blockDim.x + threadIdx.x;   // 16384
    float v = W[idx];
    __nv_bfloat16 h = __float2bfloat16(v);
    hi[idx] = h;
    lo[idx] = __float2bfloat16(v - __bfloat162float(h));
}

// ---------------- preproc ----------------
__global__ void __launch_bounds__(128) k_pre(
    const float* __restrict__ x,
    const float* __restrict__ Wp, const float* __restrict__ bp,
    const float* __restrict__ W1, const float* __restrict__ b1,
    const float* __restrict__ W2, const float* __restrict__ b2)
{
    __shared__ float sWp[8 * 32];
    __shared__ float sW1[32 * 128];
    __shared__ float sW2[32 * 128];
    __shared__ float sbp[32], sb1[128], sb2[128];
    __shared__ float xs[32][8];
    __shared__ float h0s[32][33];

    int tid = threadIdx.x;
    for (int i = tid; i < 8 * 32; i += 128) sWp[i] = Wp[i];
    for (int i = tid; i < 32 * 128; i += 128) { sW1[i] = W1[i]; sW2[i] = W2[i]; }
    if (tid < 32) sbp[tid] = bp[tid];
    sb1[tid] = b1[tid];
    sb2[tid] = b2[tid];

    int n0 = blockIdx.x * 32;
    for (int i = tid; i < 32 * 8; i += 128) {
        int n = i >> 3, f = i & 7;
        xs[n][f] = x[(size_t)(n0 + n) * 8 + f];
    }
    __syncthreads();

    for (int i = tid; i < 32 * 32; i += 128) {
        int n = i >> 5, j = i & 31;
        float s = sbp[j];
        #pragma unroll
        for (int f = 0; f < 8; f++) s = fmaf(xs[n][f], sWp[f * 32 + j], s);
        h0s[n][j] = s;
    }
    __syncthreads();

    int c = tid;
    for (int n = 0; n < 32; n++) {
        int row = n0 + n;
        float s1 = sb1[c], s2 = sb2[c];
        #pragma unroll
        for (int k = 0; k < 32; k++) {
            float hv = h0s[n][k];
            s1 = fmaf(hv, sW1[k * 128 + c], s1);
            s2 = fmaf(hv, sW2[k * 128 + c], s2);
        }
        g_ni[(size_t)row * C + c] = fmaxf(s1, 0.f);
        g_h [(size_t)row * C + c] = fmaxf(s2, 0.f);
    }
}

// ---------------- HMMA GEMM: out[M,128] = A[M,128] @ W[128,128] + epilogue ----------------
// 3-term bf16 split: Ah*Bh + Ah*Bl + Al*Bh, fp32 accumulators.
// MODE 0: out = acc * dis[row];  MODE 1: out = relu(acc + P[row,:]);  MODE 2: out = acc + bias[:]
#define LDROW 272                       // 136 bf16 per row (128 + 8 pad) -> conflict-free ldmatrix
#define SM_AH 0
#define SM_AL (SM_AH + 128 * LDROW)     // 34816
#define SM_BH (SM_AL + 128 * LDROW)     // 69632
#define SM_BL (SM_BH + 128 * LDROW)     // 104448
#define SM_TOT (SM_BL + 128 * LDROW)    // 139264

template<int MODE>
__global__ void __launch_bounds__(256) k_tgemm(
    const float* __restrict__ A,
    const __nv_bfloat16* __restrict__ Bhi, const __nv_bfloat16* __restrict__ Blo,
    const float* __restrict__ BP, float* __restrict__ out)
{
    extern __shared__ __align__(128) char smem[];
    uint32_t sb = smem_u32(smem);
    int t = threadIdx.x;
    int m0 = blockIdx.x * 128;

    // --- A fp32 -> bf16 hi/lo into padded smem ---
    #pragma unroll 4
    for (int it = 0; it < 16; it++) {
        int idx = it * 256 + t;          // 0..4095
        int row = idx >> 5;              // 0..127
        int seg = idx & 31;              // 0..31 (4 floats each)
        int grow = m0 + row;
        float4 v = make_float4(0.f, 0.f, 0.f, 0.f);
        if (grow < N_NODES) v = *(const float4*)&A[(size_t)grow * C + seg * 4];
        __nv_bfloat16 h0 = __float2bfloat16(v.x), h1 = __float2bfloat16(v.y);
        __nv_bfloat16 h2 = __float2bfloat16(v.z), h3 = __float2bfloat16(v.w);
        __nv_bfloat162 hA(h0, h1), hB(h2, h3);
        __nv_bfloat162 lA(__float2bfloat16(v.x - __bfloat162float(h0)),
                          __float2bfloat16(v.y - __bfloat162float(h1)));
        __nv_bfloat162 lB(__float2bfloat16(v.z - __bfloat162float(h2)),
                          __float2bfloat16(v.w - __bfloat162float(h3)));
        char* ph = smem + SM_AH + row * LDROW + seg * 8;
        char* pl = smem + SM_AL + row * LDROW + seg * 8;
        *(__nv_bfloat162*)(ph)     = hA;
        *(__nv_bfloat162*)(ph + 4) = hB;
        *(__nv_bfloat162*)(pl)     = lA;
        *(__nv_bfloat162*)(pl + 4) = lB;
    }
    // --- B bf16 hi/lo copy into padded smem ---
    #pragma unroll 4
    for (int it = 0; it < 8; it++) {
        int idx = it * 256 + t;          // 0..2047
        int row = idx >> 4;              // 0..127 (k)
        int seg = idx & 15;              // 8 bf16 each
        *(uint4*)(smem + SM_BH + row * LDROW + seg * 16) = *(const uint4*)&Bhi[row * 128 + seg * 8];
        *(uint4*)(smem + SM_BL + row * LDROW + seg * 16) = *(const uint4*)&Blo[row * 128 + seg * 8];
    }
    __syncthreads();

    int wid = t >> 5, lane = t & 31;
    int mw = (wid & 1) * 64;             // warp m-offset
    int nw = (wid >> 1) * 32;            // warp n-offset
    int arow = lane & 15, acb = lane >> 4;

    float acc[4][4][4];
    #pragma unroll
    for (int i = 0; i < 4; i++)
        #pragma unroll
        for (int j = 0; j < 4; j++)
            #pragma unroll
            for (int e = 0; e < 4; e++) acc[i][j][e] = 0.f;

    const int SA[3] = { SM_AH, SM_AH, SM_AL };
    const int SB[3] = { SM_BH, SM_BL, SM_BH };

    #pragma unroll
    for (int ps = 0; ps < 3; ps++) {
        uint32_t sa = sb + SA[ps];
        uint32_t sbB = sb + SB[ps];
        #pragma unroll
        for (int kc = 0; kc < 8; kc++) {
            int k0 = kc * 16;
            uint32_t afr[4][4];
            #pragma unroll
            for (int mt = 0; mt < 4; mt++)
                LDSM_X4(afr[mt], sa + (uint32_t)(mw + mt * 16 + arow) * LDROW + acb * 16 + k0 * 2);
            uint32_t bfr[2][4];
            #pragma unroll
            for (int np = 0; np < 2; np++)
                LDSM_X4T(bfr[np], sbB + (uint32_t)(k0 + arow) * LDROW + (nw + np * 16 + acb * 8) * 2);
            #pragma unroll
            for (int mt = 0; mt < 4; mt++)
                #pragma unroll
                for (int nt = 0; nt < 4; nt++)
                    mma_bf16(acc[mt][nt], afr[mt], &bfr[nt >> 1][(nt & 1) * 2]);
        }
    }

    // --- epilogue ---
    int gid = lane >> 2, t4 = lane & 3;
    #pragma unroll
    for (int mt = 0; mt < 4; mt++) {
        int r0 = m0 + mw + mt * 16 + gid;
        int r1 = r0 + 8;
        bool v0 = r0 < N_NODES, v1 = r1 < N_NODES;
        float d0 = 0.f, d1 = 0.f;
        if (MODE == 0) { if (v0) d0 = g_dis[r0]; if (v1) d1 = g_dis[r1]; }
        #pragma unroll
        for (int nt = 0; nt < 4; nt++) {
            int col = nw + nt * 8 + t4 * 2;
            float* a = acc[mt][nt];
            if (MODE == 0) {
                if (v0) *(float2*)&out[(size_t)r0 * C + col] = make_float2(a[0] * d0, a[1] * d0);
                if (v1) *(float2*)&out[(size_t)r1 * C + col] = make_float2(a[2] * d1, a[3] * d1);
            } else if (MODE == 1) {
                if (v0) {
                    float2 p = *(const float2*)&BP[(size_t)r0 * C + col];
                    *(float2*)&out[(size_t)r0 * C + col] =
                        make_float2(fmaxf(a[0] + p.x, 0.f), fmaxf(a[1] + p.y, 0.f));
                }
                if (v1) {
                    float2 p = *(const float2*)&BP[(size_t)r1 * C + col];
                    *(float2*)&out[(size_t)r1 * C + col] =
                        make_float2(fmaxf(a[2] + p.x, 0.f), fmaxf(a[3] + p.y, 0.f));
                }
            } else {
                float2 bb = *(const float2*)&BP[col];
                if (v0) *(float2*)&out[(size_t)r0 * C + col] = make_float2(a[0] + bb.x, a[1] + bb.y);
                if (v1) *(float2*)&out[(size_t)r1 * C + col] = make_float2(a[2] + bb.x, a[3] + bb.y);
            }
        }
    }
}

// ---------------- aggregation ----------------
__global__ void __launch_bounds__(256) k_agg(const float* __restrict__ bg) {
    int gt = blockIdx.x * blockDim.x + threadIdx.x;
    int w = gt >> 5;
    if (w >= N_NODES) return;
    int lane = threadIdx.x & 31;

    int base = g_rowptr[w];
    int deg  = g_deg[w];

    float4 acc = *(const float4*)&g_hs[(size_t)w * C + lane * 4];   // self-loop

    int j = 0;
    for (; j + 4 <= deg; j += 4) {
        int s0 = g_csrsrc[base + j];
        int s1 = g_csrsrc[base + j + 1];
        int s2 = g_csrsrc[base + j + 2];
        int s3 = g_csrsrc[base + j + 3];
        float4 v0 = *(const float4*)&g_hs[(size_t)s0 * C + lane * 4];
        float4 v1 = *(const float4*)&g_hs[(size_t)s1 * C + lane * 4];
        float4 v2 = *(const float4*)&g_hs[(size_t)s2 * C + lane * 4];
        float4 v3 = *(const float4*)&g_hs[(size_t)s3 * C + lane * 4];
        acc.x += v0.x + v1.x + v2.x + v3.x;
        acc.y += v0.y + v1.y + v2.y + v3.y;
        acc.z += v0.z + v1.z + v2.z + v3.z;
        acc.w += v0.w + v1.w + v2.w + v3.w;
    }
    for (; j < deg; j++) {
        int s = g_csrsrc[base + j];
        float4 v = *(const float4*)&g_hs[(size_t)s * C + lane * 4];
        acc.x += v.x; acc.y += v.y; acc.z += v.z; acc.w += v.w;
    }

    float d = g_dis[w];
    float4 bb = *(const float4*)&bg[lane * 4];
    float4 r;
    r.x = fmaxf(fmaf(acc.x, d, bb.x), 0.f);
    r.y = fmaxf(fmaf(acc.y, d, bb.y), 0.f);
    r.z = fmaxf(fmaf(acc.z, d, bb.z), 0.f);
    r.w = fmaxf(fmaf(acc.w, d, bb.w), 0.f);
    *(float4*)&g_g[(size_t)w * C + lane * 4] = r;
}

// ---------------- output head ----------------
__global__ void __launch_bounds__(256) k_out(
    const float* __restrict__ Wf2, const float* __restrict__ bf2, float* __restrict__ out)
{
    int gt = blockIdx.x * blockDim.x + threadIdx.x;
    int w = gt >> 5;
    if (w >= N_NODES) return;
    int lane = threadIdx.x & 31;

    float4 h = *(const float4*)&g_h2[(size_t)w * C + lane * 4];
    float4 w01 = *(const float4*)&Wf2[lane * 8];
    float4 w23 = *(const float4*)&Wf2[lane * 8 + 4];

    float s0 = h.x * w01.x + h.y * w01.z + h.z * w23.x + h.w * w23.z;
    float s1 = h.x * w01.y + h.y * w01.w + h.z * w23.y + h.w * w23.w;

    #pragma unroll
    for (int off = 16; off > 0; off >>= 1) {
        s0 += __shfl_xor_sync(0xFFFFFFFF, s0, off);
        s1 += __shfl_xor_sync(0xFFFFFFFF, s1, off);
    }
    if (lane == 0) {
        out[(size_t)w * 2 + 0] = s0 + bf2[0];
        out[(size_t)w * 2 + 1] = s1 + bf2[1];
    }
}

// ---------------- host launcher ----------------
extern "C" void kernel_launch(void* const* d_in, const int* in_sizes, int n_in,
                              void* d_out, int out_size)
{
    const float* x   = (const float*)d_in[0];
    const int* ei    = (const int*)d_in[1];
    const float* Wp  = (const float*)d_in[2];
    const float* bp  = (const float*)d_in[3];
    const float* W1  = (const float*)d_in[4];
    const float* b1  = (const float*)d_in[5];
    const float* W2  = (const float*)d_in[6];
    const float* b2  = (const float*)d_in[7];
    const float* Wg  = (const float*)d_in[8];
    const float* bg  = (const float*)d_in[9];
    const float* Wd  = (const float*)d_in[10];
    const float* bd  = (const float*)d_in[11];
    const float* Wf1 = (const float*)d_in[12];
    const float* bf1 = (const float*)d_in[13];
    const float* Wf2 = (const float*)d_in[14];
    const float* bf2 = (const float*)d_in[15];
    float* out = (float*)d_out;

    const int* src = ei;
    const int* dst = ei + N_EDGES;

    float* d_ni = nullptr;   cudaGetSymbolAddress((void**)&d_ni,   g_ni);
    float* d_h  = nullptr;   cudaGetSymbolAddress((void**)&d_h,    g_h);
    float* d_hs = nullptr;   cudaGetSymbolAddress((void**)&d_hs,   g_hs);
    float* d_g  = nullptr;   cudaGetSymbolAddress((void**)&d_g,    g_g);
    float* d_h2 = nullptr;   cudaGetSymbolAddress((void**)&d_h2,   g_h2);
    float* d_pre = nullptr;  cudaGetSymbolAddress((void**)&d_pre,  g_pre);
    float* d_pref = nullptr; cudaGetSymbolAddress((void**)&d_pref, g_pref);
    __nv_bfloat16* d_whi = nullptr; cudaGetSymbolAddress((void**)&d_whi, g_whi);
    __nv_bfloat16* d_wlo = nullptr; cudaGetSymbolAddress((void**)&d_wlo, g_wlo);

    cudaFuncSetAttribute(k_tgemm<0>, cudaFuncAttributeMaxDynamicSharedMemorySize, SM_TOT);
    cudaFuncSetAttribute(k_tgemm<1>, cudaFuncAttributeMaxDynamicSharedMemorySize, SM_TOT);
    cudaFuncSetAttribute(k_tgemm<2>, cudaFuncAttributeMaxDynamicSharedMemorySize, SM_TOT);

    const int MB  = (N_NODES + 127) / 128;        // 782
    const int WPB = (N_NODES * 32 + 255) / 256;

    const float* wsrc[5] = { Wg, Wd, Wd + 128 * C, Wf1, Wf1 + 128 * C };

    // order: 6th launch (ncu -s 5 -c 1 capture) is a GEMM
    k_zero_nodes<<<(N_NODES + 255) / 256, 256>>>();                       // 1
    k_pre<<<N_NODES / 32, 128>>>(x, Wp, bp, W1, b1, W2, b2);              // 2
    k_wprep<<<64, 256>>>(wsrc[1], d_whi + 1 * 16384, d_wlo + 1 * 16384);  // 3 (WdA)
    k_wprep<<<64, 256>>>(wsrc[3], d_whi + 3 * 16384, d_wlo + 3 * 16384);  // 4 (Wf1A)
    k_wprep<<<64, 256>>>(wsrc[0], d_whi + 0 * 16384, d_wlo + 0 * 16384);  // 5 (Wg)
    k_tgemm<2><<<MB, 256, SM_TOT>>>(d_ni, d_whi + 1 * 16384, d_wlo + 1 * 16384, bd, d_pre);   // 6 <- ncu
    k_wprep<<<64, 256>>>(wsrc[2], d_whi + 2 * 16384, d_wlo + 2 * 16384);  // WdB
    k_wprep<<<64, 256>>>(wsrc[4], d_whi + 4 * 16384, d_wlo + 4 * 16384);  // Wf1B
    k_hist<<<(N_EDGES + 255) / 256, 256>>>(dst);
    k_dis<<<(N_NODES + 255) / 256, 256>>>();
    k_scan_a<<<SCAN_NB, SCAN_BLK>>>();
    k_scan_b<<<1, 32>>>();
    k_scan_c<<<SCAN_NB, SCAN_BLK>>>();
    k_fill<<<(N_EDGES + 255) / 256, 256>>>(src, dst);

    k_tgemm<2><<<MB, 256, SM_TOT>>>(d_ni, d_whi + 3 * 16384, d_wlo + 3 * 16384, bf1, d_pref);

    for (int l = 0; l < 8; l++) {
        k_tgemm<0><<<MB, 256, SM_TOT>>>(d_h, d_whi + 0 * 16384, d_wlo + 0 * 16384, nullptr, d_hs);
        k_agg<<<WPB, 256>>>(bg);
        k_tgemm<1><<<MB, 256, SM_TOT>>>(d_g, d_whi + 2 * 16384, d_wlo + 2 * 16384, d_pre, d_h);
    }

    k_tgemm<1><<<MB, 256, SM_TOT>>>(d_h, d_whi + 4 * 16384, d_wlo + 4 * 16384, d_pref, d_h2);
    k_out<<<WPB, 256>>>(Wf2, bf2, out);
}

// round 5
// speedup vs baseline: 2.0826x; 1.1439x over previous
#include <cuda_runtime.h>
#include <cuda_bf16.h>
#include <cstdint>

#define N_NODES 100000
#define N_EDGES 1600000
#define C 128

// ---------------- static scratch ----------------
__device__ float g_ni  [(size_t)N_NODES * C];
__device__ float g_h   [(size_t)N_NODES * C];   // u = h*dis (or h, after last layer)
__device__ float g_g   [(size_t)N_NODES * C];   // v = agg(u) + u
__device__ float g_h2  [(size_t)N_NODES * C];
__device__ float g_pre [(size_t)N_NODES * C];   // ni @ Wd[:128] + bd
__device__ float g_pref[(size_t)N_NODES * C];   // ni @ Wf1[:128] + bf1
__device__ float g_dis[N_NODES];
__device__ int   g_deg[N_NODES];
__device__ int   g_rowptr[N_NODES];
__device__ int   g_cursor[N_NODES];
__device__ int   g_csrsrc[N_EDGES];
__device__ int   g_bsum[128];

// bf16 hi/lo weights [k][n]: slots {0:Wg, 1:WdA, 2:WdB, 3:Wf1A, 4:Wf1B}
__device__ __nv_bfloat16 g_whi[5 * 128 * 128];
__device__ __nv_bfloat16 g_wlo[5 * 128 * 128];

#define SCAN_BLK 1024
#define SCAN_NB  ((N_NODES + SCAN_BLK - 1) / SCAN_BLK)

// ---------------- PTX helpers ----------------
__device__ __forceinline__ uint32_t smem_u32(const void* p) {
    uint32_t a;
    asm("{ .reg .u64 t; cvta.to.shared.u64 t, %1; cvt.u32.u64 %0, t; }" : "=r"(a) : "l"(p));
    return a;
}
#define LDSM_X4(r, addr) \
    asm volatile("ldmatrix.sync.aligned.m8n8.x4.shared.b16 {%0,%1,%2,%3}, [%4];" \
        : "=r"((r)[0]), "=r"((r)[1]), "=r"((r)[2]), "=r"((r)[3]) : "r"(addr))
#define LDSM_X4T(r, addr) \
    asm volatile("ldmatrix.sync.aligned.m8n8.x4.trans.shared.b16 {%0,%1,%2,%3}, [%4];" \
        : "=r"((r)[0]), "=r"((r)[1]), "=r"((r)[2]), "=r"((r)[3]) : "r"(addr))
__device__ __forceinline__ void mma_bf16(float* c, const uint32_t* a, const uint32_t* b) {
    asm volatile("mma.sync.aligned.m16n8k16.row.col.f32.bf16.bf16.f32 "
        "{%0,%1,%2,%3}, {%4,%5,%6,%7}, {%8,%9}, {%0,%1,%2,%3};"
        : "+f"(c[0]), "+f"(c[1]), "+f"(c[2]), "+f"(c[3])
        : "r"(a[0]), "r"(a[1]), "r"(a[2]), "r"(a[3]), "r"(b[0]), "r"(b[1]));
}

// ---------------- CSR build ----------------
__global__ void k_zero_nodes() {
    int i = blockIdx.x * blockDim.x + threadIdx.x;
    if (i < N_NODES) { g_deg[i] = 0; g_cursor[i] = 0; }
}
__global__ void k_hist(const int* __restrict__ dst) {
    int e = blockIdx.x * blockDim.x + threadIdx.x;
    if (e < N_EDGES) atomicAdd(&g_deg[dst[e]], 1);
}
__global__ void k_dis() {
    int i = blockIdx.x * blockDim.x + threadIdx.x;
    if (i < N_NODES) g_dis[i] = rsqrtf((float)g_deg[i] + 1.0f);
}
__global__ void __launch_bounds__(SCAN_BLK) k_scan_a() {
    __shared__ int s[SCAN_BLK];
    int tid = threadIdx.x;
    int i = blockIdx.x * SCAN_BLK + tid;
    int v = (i < N_NODES) ? g_deg[i] : 0;
    s[tid] = v;
    __syncthreads();
    #pragma unroll
    for (int off = 1; off < SCAN_BLK; off <<= 1) {
        int t = (tid >= off) ? s[tid - off] : 0;
        __syncthreads();
        s[tid] += t;
        __syncthreads();
    }
    int incl = s[tid];
    if (i < N_NODES) g_rowptr[i] = incl - v;
    if (tid == SCAN_BLK - 1) g_bsum[blockIdx.x] = incl;
}
__global__ void k_scan_b() {
    if (threadIdx.x == 0 && blockIdx.x == 0) {
        int run = 0;
        for (int b = 0; b < SCAN_NB; b++) { int t = g_bsum[b]; g_bsum[b] = run; run += t; }
    }
}
__global__ void __launch_bounds__(SCAN_BLK) k_scan_c() {
    int i = blockIdx.x * SCAN_BLK + threadIdx.x;
    if (i < N_NODES) g_rowptr[i] += g_bsum[blockIdx.x];
}
__global__ void k_fill(const int* __restrict__ src, const int* __restrict__ dst) {
    int e = blockIdx.x * blockDim.x + threadIdx.x;
    if (e < N_EDGES) {
        int d = dst[e];
        int pos = atomicAdd(&g_cursor[d], 1);
        g_csrsrc[g_rowptr[d] + pos] = src[e];
    }
}

// ---------------- weight prep ----------------
__global__ void k_wprep(const float* __restrict__ W, __nv_bfloat16* __restrict__ hi,
                        __nv_bfloat16* __restrict__ lo) {
    int idx = blockIdx.x * blockDim.x + threadIdx.x;
    float v = W[idx];
    __nv_bfloat16 h = __float2bfloat16(v);
    hi[idx] = h;
    lo[idx] = __float2bfloat16(v - __bfloat162float(h));
}

// ---------------- preproc: writes ni and u = relu(h0@W2+b2)*dis ----------------
__global__ void __launch_bounds__(128) k_pre(
    const float* __restrict__ x,
    const float* __restrict__ Wp, const float* __restrict__ bp,
    const float* __restrict__ W1, const float* __restrict__ b1,
    const float* __restrict__ W2, const float* __restrict__ b2)
{
    __shared__ float sWp[8 * 32];
    __shared__ float sW1[32 * 128];
    __shared__ float sW2[32 * 128];
    __shared__ float sbp[32], sb1[128], sb2[128];
    __shared__ float xs[32][8];
    __shared__ float h0s[32][33];

    int tid = threadIdx.x;
    for (int i = tid; i < 8 * 32; i += 128) sWp[i] = Wp[i];
    for (int i = tid; i < 32 * 128; i += 128) { sW1[i] = W1[i]; sW2[i] = W2[i]; }
    if (tid < 32) sbp[tid] = bp[tid];
    sb1[tid] = b1[tid];
    sb2[tid] = b2[tid];

    int n0 = blockIdx.x * 32;
    for (int i = tid; i < 32 * 8; i += 128) {
        int n = i >> 3, f = i & 7;
        xs[n][f] = x[(size_t)(n0 + n) * 8 + f];
    }
    __syncthreads();

    for (int i = tid; i < 32 * 32; i += 128) {
        int n = i >> 5, j = i & 31;
        float s = sbp[j];
        #pragma unroll
        for (int f = 0; f < 8; f++) s = fmaf(xs[n][f], sWp[f * 32 + j], s);
        h0s[n][j] = s;
    }
    __syncthreads();

    int c = tid;
    for (int n = 0; n < 32; n++) {
        int row = n0 + n;
        float s1 = sb1[c], s2 = sb2[c];
        #pragma unroll
        for (int k = 0; k < 32; k++) {
            float hv = h0s[n][k];
            s1 = fmaf(hv, sW1[k * 128 + c], s1);
            s2 = fmaf(hv, sW2[k * 128 + c], s2);
        }
        g_ni[(size_t)row * C + c] = fmaxf(s1, 0.f);
        g_h [(size_t)row * C + c] = fmaxf(s2, 0.f) * g_dis[row];
    }
}

// ---------------- GEMM building blocks ----------------
#define LDROW 272
#define TILE_B (128 * LDROW)   // 34816

// load 128x128 fp32 tile -> bf16 hi/lo split into padded smem
__device__ __forceinline__ void load_A_split(char* smem, int smA_h, int smA_l,
                                             const float* __restrict__ A, int m0, int t)
{
    #pragma unroll 4
    for (int it = 0; it < 16; it++) {
        int idx = it * 256 + t;
        int row = idx >> 5;
        int seg = idx & 31;
        int grow = m0 + row;
        float4 v = make_float4(0.f, 0.f, 0.f, 0.f);
        if (grow < N_NODES) v = *(const float4*)&A[(size_t)grow * C + seg * 4];
        __nv_bfloat16 h0 = __float2bfloat16(v.x), h1 = __float2bfloat16(v.y);
        __nv_bfloat16 h2 = __float2bfloat16(v.z), h3 = __float2bfloat16(v.w);
        __nv_bfloat162 hA(h0, h1), hB(h2, h3);
        __nv_bfloat162 lA(__float2bfloat16(v.x - __bfloat162float(h0)),
                          __float2bfloat16(v.y - __bfloat162float(h1)));
        __nv_bfloat162 lB(__float2bfloat16(v.z - __bfloat162float(h2)),
                          __float2bfloat16(v.w - __bfloat162float(h3)));
        char* ph = smem + smA_h + row * LDROW + seg * 8;
        char* pl = smem + smA_l + row * LDROW + seg * 8;
        *(__nv_bfloat162*)(ph)     = hA;
        *(__nv_bfloat162*)(ph + 4) = hB;
        *(__nv_bfloat162*)(pl)     = lA;
        *(__nv_bfloat162*)(pl + 4) = lB;
    }
}

// copy a 128x128 bf16 weight tile into padded smem
__device__ __forceinline__ void load_W(char* smem, int dst, const __nv_bfloat16* __restrict__ W, int t)
{
    #pragma unroll 4
    for (int it = 0; it < 8; it++) {
        int idx = it * 256 + t;
        int row = idx >> 4;
        int seg = idx & 15;
        *(uint4*)(smem + dst + row * LDROW + seg * 16) = *(const uint4*)&W[row * 128 + seg * 8];
    }
}

// 3-pass bf16-split 128x128x128 mainloop; acc += A @ B
__device__ __forceinline__ void gemm_main(uint32_t sb, int smA_h, int smA_l, int smB_h, int smB_l,
                                          int mw, int nw, int arow, int acb, float acc[4][4][4])
{
    #pragma unroll
    for (int kc = 0; kc < 8; kc++) {
        int k0 = kc * 16;
        uint32_t ah[4][4], al[4][4], bh[2][4], bl[2][4];
        #pragma unroll
        for (int mt = 0; mt < 4; mt++) {
            uint32_t ra = (uint32_t)(mw + mt * 16 + arow) * LDROW + acb * 16 + k0 * 2;
            LDSM_X4(ah[mt], sb + smA_h + ra);
            LDSM_X4(al[mt], sb + smA_l + ra);
        }
        #pragma unroll
        for (int np = 0; np < 2; np++) {
            uint32_t rb = (uint32_t)(k0 + arow) * LDROW + (nw + np * 16 + acb * 8) * 2;
            LDSM_X4T(bh[np], sb + smB_h + rb);
            LDSM_X4T(bl[np], sb + smB_l + rb);
        }
        #pragma unroll
        for (int mt = 0; mt < 4; mt++)
            #pragma unroll
            for (int nt = 0; nt < 4; nt++) {
                mma_bf16(acc[mt][nt], ah[mt], &bh[nt >> 1][(nt & 1) * 2]);
                mma_bf16(acc[mt][nt], ah[mt], &bl[nt >> 1][(nt & 1) * 2]);
                mma_bf16(acc[mt][nt], al[mt], &bh[nt >> 1][(nt & 1) * 2]);
            }
    }
}

// ---------------- standalone GEMM ----------------
// MODE 1: out = relu(acc + P[row,:]);  MODE 2: out = acc + bias[:]
#define SM_AH 0
#define SM_AL (SM_AH + TILE_B)
#define SM_BH (SM_AL + TILE_B)
#define SM_BL (SM_BH + TILE_B)
#define SM_TOT (SM_BL + TILE_B)

template<int MODE>
__global__ void __launch_bounds__(256) k_tgemm(
    const float* __restrict__ A,
    const __nv_bfloat16* __restrict__ Bhi, const __nv_bfloat16* __restrict__ Blo,
    const float* __restrict__ BP, float* __restrict__ out)
{
    extern __shared__ __align__(128) char smem[];
    uint32_t sb = smem_u32(smem);
    int t = threadIdx.x;
    int m0 = blockIdx.x * 128;

    load_A_split(smem, SM_AH, SM_AL, A, m0, t);
    load_W(smem, SM_BH, Bhi, t);
    load_W(smem, SM_BL, Blo, t);
    __syncthreads();

    int wid = t >> 5, lane = t & 31;
    int mw = (wid & 1) * 64, nw = (wid >> 1) * 32;
    int arow = lane & 15, acb = lane >> 4;

    float acc[4][4][4];
    #pragma unroll
    for (int i = 0; i < 4; i++)
        #pragma unroll
        for (int j = 0; j < 4; j++) { acc[i][j][0] = acc[i][j][1] = acc[i][j][2] = acc[i][j][3] = 0.f; }

    gemm_main(sb, SM_AH, SM_AL, SM_BH, SM_BL, mw, nw, arow, acb, acc);

    int gid = lane >> 2, t4 = lane & 3;
    #pragma unroll
    for (int mt = 0; mt < 4; mt++) {
        int r0 = m0 + mw + mt * 16 + gid;
        int r1 = r0 + 8;
        bool v0 = r0 < N_NODES, v1 = r1 < N_NODES;
        #pragma unroll
        for (int nt = 0; nt < 4; nt++) {
            int col = nw + nt * 8 + t4 * 2;
            float* a = acc[mt][nt];
            if (MODE == 1) {
                if (v0) {
                    float2 p = *(const float2*)&BP[(size_t)r0 * C + col];
                    *(float2*)&out[(size_t)r0 * C + col] =
                        make_float2(fmaxf(a[0] + p.x, 0.f), fmaxf(a[1] + p.y, 0.f));
                }
                if (v1) {
                    float2 p = *(const float2*)&BP[(size_t)r1 * C + col];
                    *(float2*)&out[(size_t)r1 * C + col] =
                        make_float2(fmaxf(a[2] + p.x, 0.f), fmaxf(a[3] + p.y, 0.f));
                }
            } else {
                float2 bb = *(const float2*)&BP[col];
                if (v0) *(float2*)&out[(size_t)r0 * C + col] = make_float2(a[0] + bb.x, a[1] + bb.y);
                if (v1) *(float2*)&out[(size_t)r1 * C + col] = make_float2(a[2] + bb.x, a[3] + bb.y);
            }
        }
    }
}

// ---------------- fused layer kernel ----------------
// g = relu((V@Wg)*dis + bg)  [smem, bf16 split];  out = relu(g@WdB + pre) * (LAST ? 1 : dis)
#define SF_AH 0
#define SF_AL (SF_AH + TILE_B)
#define SF_W1H (SF_AL + TILE_B)
#define SF_W1L (SF_W1H + TILE_B)
#define SF_W2H (SF_W1L + TILE_B)
#define SF_W2L (SF_W2H + TILE_B)
#define SF_TOT (SF_W2L + TILE_B)    // 208896

template<bool LAST>
__global__ void __launch_bounds__(256) k_layer(
    const float* __restrict__ V, const float* __restrict__ bg,
    const float* __restrict__ P, float* __restrict__ out)
{
    extern __shared__ __align__(128) char smem[];
    uint32_t sb = smem_u32(smem);
    int t = threadIdx.x;
    int m0 = blockIdx.x * 128;

    load_A_split(smem, SF_AH, SF_AL, V, m0, t);
    load_W(smem, SF_W1H, g_whi + 0 * 16384, t);   // Wg hi
    load_W(smem, SF_W1L, g_wlo + 0 * 16384, t);   // Wg lo
    load_W(smem, SF_W2H, g_whi + 2 * 16384, t);   // WdB hi
    load_W(smem, SF_W2L, g_wlo + 2 * 16384, t);   // WdB lo
    __syncthreads();

    int wid = t >> 5, lane = t & 31;
    int mw = (wid & 1) * 64, nw = (wid >> 1) * 32;
    int arow = lane & 15, acb = lane >> 4;
    int gid = lane >> 2, t4 = lane & 3;

    float acc[4][4][4];
    #pragma unroll
    for (int i = 0; i < 4; i++)
        #pragma unroll
        for (int j = 0; j < 4; j++) { acc[i][j][0] = acc[i][j][1] = acc[i][j][2] = acc[i][j][3] = 0.f; }

    // GEMM1: V @ Wg
    gemm_main(sb, SF_AH, SF_AL, SF_W1H, SF_W1L, mw, nw, arow, acb, acc);

    __syncthreads();   // all warps done reading A region

    // epilogue1: g = relu(acc*dis + bg) -> bf16 hi/lo into A region
    #pragma unroll
    for (int mt = 0; mt < 4; mt++) {
        int lr0 = mw + mt * 16 + gid;
        int lr1 = lr0 + 8;
        int gr0 = m0 + lr0, gr1 = m0 + lr1;
        float d0 = (gr0 < N_NODES) ? g_dis[gr0] : 0.f;
        float d1 = (gr1 < N_NODES) ? g_dis[gr1] : 0.f;
        #pragma unroll
        for (int nt = 0; nt < 4; nt++) {
            int col = nw + nt * 8 + t4 * 2;
            float2 bb = *(const float2*)&bg[col];
            float* a = acc[mt][nt];
            float g00 = fmaxf(fmaf(a[0], d0, bb.x), 0.f);
            float g01 = fmaxf(fmaf(a[1], d0, bb.y), 0.f);
            float g10 = fmaxf(fmaf(a[2], d1, bb.x), 0.f);
            float g11 = fmaxf(fmaf(a[3], d1, bb.y), 0.f);
            __nv_bfloat16 h00 = __float2bfloat16(g00), h01 = __float2bfloat16(g01);
            __nv_bfloat16 h10 = __float2bfloat16(g10), h11 = __float2bfloat16(g11);
            *(__nv_bfloat162*)(smem + SF_AH + lr0 * LDROW + col * 2) = __nv_bfloat162(h00, h01);
            *(__nv_bfloat162*)(smem + SF_AH + lr1 * LDROW + col * 2) = __nv_bfloat162(h10, h11);
            *(__nv_bfloat162*)(smem + SF_AL + lr0 * LDROW + col * 2) =
                __nv_bfloat162(__float2bfloat16(g00 - __bfloat162float(h00)),
                               __float2bfloat16(g01 - __bfloat162float(h01)));
            *(__nv_bfloat162*)(smem + SF_AL + lr1 * LDROW + col * 2) =
                __nv_bfloat162(__float2bfloat16(g10 - __bfloat162float(h10)),
                               __float2bfloat16(g11 - __bfloat162float(h11)));
        }
    }
    __syncthreads();

    #pragma unroll
    for (int i = 0; i < 4; i++)
        #pragma unroll
        for (int j = 0; j < 4; j++) { acc[i][j][0] = acc[i][j][1] = acc[i][j][2] = acc[i][j][3] = 0.f; }

    // GEMM2: g @ WdB
    gemm_main(sb, SF_AH, SF_AL, SF_W2H, SF_W2L, mw, nw, arow, acb, acc);

    // epilogue2: out = relu(acc + pre) * (LAST ? 1 : dis)
    #pragma unroll
    for (int mt = 0; mt < 4; mt++) {
        int gr0 = m0 + mw + mt * 16 + gid;
        int gr1 = gr0 + 8;
        bool v0 = gr0 < N_NODES, v1 = gr1 < N_NODES;
        float d0 = 1.f, d1 = 1.f;
        if (!LAST) {
            if (v0) d0 = g_dis[gr0];
            if (v1) d1 = g_dis[gr1];
        }
        #pragma unroll
        for (int nt = 0; nt < 4; nt++) {
            int col = nw + nt * 8 + t4 * 2;
            float* a = acc[mt][nt];
            if (v0) {
                float2 p = *(const float2*)&P[(size_t)gr0 * C + col];
                *(float2*)&out[(size_t)gr0 * C + col] =
                    make_float2(fmaxf(a[0] + p.x, 0.f) * d0, fmaxf(a[1] + p.y, 0.f) * d0);
            }
            if (v1) {
                float2 p = *(const float2*)&P[(size_t)gr1 * C + col];
                *(float2*)&out[(size_t)gr1 * C + col] =
                    make_float2(fmaxf(a[2] + p.x, 0.f) * d1, fmaxf(a[3] + p.y, 0.f) * d1);
            }
        }
    }
}

// ---------------- aggregation: v = u[w] + sum_{j in N(w)} u[j] ----------------
__global__ void __launch_bounds__(256) k_agg() {
    int gt = blockIdx.x * blockDim.x + threadIdx.x;
    int w = gt >> 5;
    if (w >= N_NODES) return;
    int lane = threadIdx.x & 31;

    int base = g_rowptr[w];
    int deg  = g_deg[w];

    float4 acc = *(const float4*)&g_h[(size_t)w * C + lane * 4];   // self

    int j = 0;
    for (; j + 4 <= deg; j += 4) {
        int s0 = g_csrsrc[base + j];
        int s1 = g_csrsrc[base + j + 1];
        int s2 = g_csrsrc[base + j + 2];
        int s3 = g_csrsrc[base + j + 3];
        float4 v0 = *(const float4*)&g_h[(size_t)s0 * C + lane * 4];
        float4 v1 = *(const float4*)&g_h[(size_t)s1 * C + lane * 4];
        float4 v2 = *(const float4*)&g_h[(size_t)s2 * C + lane * 4];
        float4 v3 = *(const float4*)&g_h[(size_t)s3 * C + lane * 4];
        acc.x += v0.x + v1.x + v2.x + v3.x;
        acc.y += v0.y + v1.y + v2.y + v3.y;
        acc.z += v0.z + v1.z + v2.z + v3.z;
        acc.w += v0.w + v1.w + v2.w + v3.w;
    }
    for (; j < deg; j++) {
        int s = g_csrsrc[base + j];
        float4 v = *(const float4*)&g_h[(size_t)s * C + lane * 4];
        acc.x += v.x; acc.y += v.y; acc.z += v.z; acc.w += v.w;
    }
    *(float4*)&g_g[(size_t)w * C + lane * 4] = acc;
}

// ---------------- output head ----------------
__global__ void __launch_bounds__(256) k_out(
    const float* __restrict__ Wf2, const float* __restrict__ bf2, float* __restrict__ out)
{
    int gt = blockIdx.x * blockDim.x + threadIdx.x;
    int w = gt >> 5;
    if (w >= N_NODES) return;
    int lane = threadIdx.x & 31;

    float4 h = *(const float4*)&g_h2[(size_t)w * C + lane * 4];
    float4 w01 = *(const float4*)&Wf2[lane * 8];
    float4 w23 = *(const float4*)&Wf2[lane * 8 + 4];

    float s0 = h.x * w01.x + h.y * w01.z + h.z * w23.x + h.w * w23.z;
    float s1 = h.x * w01.y + h.y * w01.w + h.z * w23.y + h.w * w23.w;

    #pragma unroll
    for (int off = 16; off > 0; off >>= 1) {
        s0 += __shfl_xor_sync(0xFFFFFFFF, s0, off);
        s1 += __shfl_xor_sync(0xFFFFFFFF, s1, off);
    }
    if (lane == 0) {
        out[(size_t)w * 2 + 0] = s0 + bf2[0];
        out[(size_t)w * 2 + 1] = s1 + bf2[1];
    }
}

// ---------------- host launcher ----------------
extern "C" void kernel_launch(void* const* d_in, const int* in_sizes, int n_in,
                              void* d_out, int out_size)
{
    const float* x   = (const float*)d_in[0];
    const int* ei    = (const int*)d_in[1];
    const float* Wp  = (const float*)d_in[2];
    const float* bp  = (const float*)d_in[3];
    const float* W1  = (const float*)d_in[4];
    const float* b1  = (const float*)d_in[5];
    const float* W2  = (const float*)d_in[6];
    const float* b2  = (const float*)d_in[7];
    const float* Wg  = (const float*)d_in[8];
    const float* bg  = (const float*)d_in[9];
    const float* Wd  = (const float*)d_in[10];
    const float* bd  = (const float*)d_in[11];
    const float* Wf1 = (const float*)d_in[12];
    const float* bf1 = (const float*)d_in[13];
    const float* Wf2 = (const float*)d_in[14];
    const float* bf2 = (const float*)d_in[15];
    float* out = (float*)d_out;

    const int* src = ei;
    const int* dst = ei + N_EDGES;

    float* d_ni = nullptr;   cudaGetSymbolAddress((void**)&d_ni,   g_ni);
    float* d_h  = nullptr;   cudaGetSymbolAddress((void**)&d_h,    g_h);
    float* d_g  = nullptr;   cudaGetSymbolAddress((void**)&d_g,    g_g);
    float* d_h2 = nullptr;   cudaGetSymbolAddress((void**)&d_h2,   g_h2);
    float* d_pre = nullptr;  cudaGetSymbolAddress((void**)&d_pre,  g_pre);
    float* d_pref = nullptr; cudaGetSymbolAddress((void**)&d_pref, g_pref);
    __nv_bfloat16* d_whi = nullptr; cudaGetSymbolAddress((void**)&d_whi, g_whi);
    __nv_bfloat16* d_wlo = nullptr; cudaGetSymbolAddress((void**)&d_wlo, g_wlo);

    cudaFuncSetAttribute(k_tgemm<1>, cudaFuncAttributeMaxDynamicSharedMemorySize, SM_TOT);
    cudaFuncSetAttribute(k_tgemm<2>, cudaFuncAttributeMaxDynamicSharedMemorySize, SM_TOT);
    cudaFuncSetAttribute(k_layer<false>, cudaFuncAttributeMaxDynamicSharedMemorySize, SF_TOT);
    cudaFuncSetAttribute(k_layer<true>,  cudaFuncAttributeMaxDynamicSharedMemorySize, SF_TOT);

    const int MB  = (N_NODES + 127) / 128;        // 782
    const int WPB = (N_NODES * 32 + 255) / 256;

    const float* wsrc[5] = { Wg, Wd, Wd + 128 * C, Wf1, Wf1 + 128 * C };

    k_zero_nodes<<<(N_NODES + 255) / 256, 256>>>();                       // 1
    k_hist<<<(N_EDGES + 255) / 256, 256>>>(dst);                          // 2
    k_dis<<<(N_NODES + 255) / 256, 256>>>();                              // 3
    k_pre<<<N_NODES / 32, 128>>>(x, Wp, bp, W1, b1, W2, b2);              // 4 (needs dis)
    k_wprep<<<64, 256>>>(wsrc[1], d_whi + 1 * 16384, d_wlo + 1 * 16384);  // 5 (WdA)
    k_tgemm<2><<<MB, 256, SM_TOT>>>(d_ni, d_whi + 1 * 16384, d_wlo + 1 * 16384, bd, d_pre); // 6 <- ncu
    k_wprep<<<64, 256>>>(wsrc[0], d_whi + 0 * 16384, d_wlo + 0 * 16384);  // Wg
    k_wprep<<<64, 256>>>(wsrc[2], d_whi + 2 * 16384, d_wlo + 2 * 16384);  // WdB
    k_wprep<<<64, 256>>>(wsrc[3], d_whi + 3 * 16384, d_wlo + 3 * 16384);  // Wf1A
    k_wprep<<<64, 256>>>(wsrc[4], d_whi + 4 * 16384, d_wlo + 4 * 16384);  // Wf1B
    k_tgemm<2><<<MB, 256, SM_TOT>>>(d_ni, d_whi + 3 * 16384, d_wlo + 3 * 16384, bf1, d_pref);
    k_scan_a<<<SCAN_NB, SCAN_BLK>>>();
    k_scan_b<<<1, 32>>>();
    k_scan_c<<<SCAN_NB, SCAN_BLK>>>();
    k_fill<<<(N_EDGES + 255) / 256, 256>>>(src, dst);

    for (int l = 0; l < 8; l++) {
        k_agg<<<WPB, 256>>>();
        if (l < 7) k_layer<false><<<MB, 256, SF_TOT>>>(d_g, bg, d_pre, d_h);
        else       k_layer<true ><<<MB, 256, SF_TOT>>>(d_g, bg, d_pre, d_h);
    }

    k_tgemm<1><<<MB, 256, SM_TOT>>>(d_h, d_whi + 4 * 16384, d_wlo + 4 * 16384, d_pref, d_h2);
    k_out<<<WPB, 256>>>(Wf2, bf2, out);
}